// round 14
// baseline (speedup 1.0000x reference)
#include <cuda_runtime.h>
#include <cuda_fp16.h>
#include <math.h>
#include <stdint.h>

#define N    8192
#define D    256
#define INV_T (1.0f / 0.7f)
#define EX2SC (1.44269504088896f * INV_T)   // log2(e)/T

#define TM 128
#define TN 128
#define GI (N / TM)                  // 64
#define NTILES (GI * (GI + 1) / 2)   // 2080

// ---------------- device scratch ----------------
__device__ __half g_Ph[N * D];       // normalized rows, f16, row-major
__device__ float g_A[N];
__device__ float g_B[N];
__device__ float g_selfsim[N];
__device__ int   g_cls[N];

// ---------------- helpers ----------------
__device__ __forceinline__ uint32_t smem_u32(const void* p) {
    uint32_t a;
    asm("{ .reg .u64 t; cvta.to.shared.u64 t, %1; cvt.u32.u64 %0, t; }"
        : "=r"(a) : "l"(p));
    return a;
}
#define SW128(off) ((off) ^ (((off) >> 3) & 0x70))

__device__ __forceinline__ void cp16(uint32_t dst, const void* src) {
    asm volatile("cp.async.cg.shared.global [%0], [%1], 16;" :: "r"(dst), "l"(src));
}
__device__ __forceinline__ void cp_commit() {
    asm volatile("cp.async.commit_group;" ::: "memory");
}
__device__ __forceinline__ void ldsm4(uint32_t& r0, uint32_t& r1,
                                      uint32_t& r2, uint32_t& r3, uint32_t addr) {
    asm volatile("ldmatrix.sync.aligned.m8n8.x4.shared.b16 {%0,%1,%2,%3}, [%4];"
                 : "=r"(r0), "=r"(r1), "=r"(r2), "=r"(r3) : "r"(addr));
}
__device__ __forceinline__ void mma16816h(uint32_t* d, const uint32_t* a,
                                          const uint32_t* b) {
    asm volatile("mma.sync.aligned.m16n8k16.row.col.f16.f16.f16.f16 "
                 "{%0,%1}, {%2,%3,%4,%5}, {%6,%7}, {%0,%1};"
                 : "+r"(d[0]), "+r"(d[1])
                 : "r"(a[0]), "r"(a[1]), "r"(a[2]), "r"(a[3]),
                   "r"(b[0]), "r"(b[1]));
}
__device__ __forceinline__ float ex2(float x) {
    float r;
    asm("ex2.approx.f32 %0, %1;" : "=f"(r) : "f"(x));
    return r;
}

// ---------------- SMEM layout: 2-deep ring of (A16KB + B16KB) chunks --------
#define ACH(b) ((b) * 16384)                 // A buf b: 128 rows x 128 B (SW128)
#define BCH(b) (32768 + (b) * 16384)         // B buf b
#define CLSI_OFF  65536
#define CLSJ_OFF  66048
#define SACCI_OFF 66560
#define SBCCI_OFF 67072
#define SACCJ_OFF 67584
#define SBCCJ_OFF 68096
#define SMEM_BYTES 68608                     // x3 CTAs = 205824 B/SM

// ---------------------------------------------------------------------------
// k_norm: dtype detect + zero A/B + normalize->f16 + selfsim + class
// ---------------------------------------------------------------------------
__global__ void k_norm(const float* __restrict__ P, const void* __restrict__ yv) {
    __shared__ int s_is64;
    const int tid  = threadIdx.x;
    const int w    = tid >> 5;
    const int lane = tid & 31;
    const int row  = blockIdx.x * 8 + w;

    if (w == 0) {   // detect: int64 y<10 => all odd 32-bit words zero
        int v = ((const int*)yv)[2 * lane + 1];
        unsigned any = __ballot_sync(0xffffffffu, v != 0);
        if (lane == 0) s_is64 = (any == 0) ? 1 : 0;
    }
    if (blockIdx.x < 32) {              // zero accumulators
        int idx = blockIdx.x * 256 + tid;
        g_A[idx] = 0.0f; g_B[idx] = 0.0f;
    }
    __syncthreads();
    const int is64 = s_is64;

    const float4* p4 = (const float4*)(P + (size_t)row * D);
    float4 v0 = p4[lane];
    float4 v1 = p4[lane + 32];

    float ss = v0.x*v0.x + v0.y*v0.y + v0.z*v0.z + v0.w*v0.w
             + v1.x*v1.x + v1.y*v1.y + v1.z*v1.z + v1.w*v1.w;
    #pragma unroll
    for (int o = 16; o; o >>= 1) ss += __shfl_xor_sync(0xffffffffu, ss, o);
    float rn = rsqrtf(ss);

    __half h[8];
    h[0] = __float2half_rn(v0.x * rn); h[1] = __float2half_rn(v0.y * rn);
    h[2] = __float2half_rn(v0.z * rn); h[3] = __float2half_rn(v0.w * rn);
    h[4] = __float2half_rn(v1.x * rn); h[5] = __float2half_rn(v1.y * rn);
    h[6] = __float2half_rn(v1.z * rn); h[7] = __float2half_rn(v1.w * rn);

    float sb = 0.0f;
    #pragma unroll
    for (int q = 0; q < 8; q++) { float f = __half2float(h[q]); sb += f * f; }
    #pragma unroll
    for (int o = 16; o; o >>= 1) sb += __shfl_xor_sync(0xffffffffu, sb, o);

    *(uint2*)(g_Ph + (size_t)row * D + lane * 4)       = *(uint2*)&h[0];
    *(uint2*)(g_Ph + (size_t)row * D + 128 + lane * 4) = *(uint2*)&h[4];

    if (lane == 0) {
        int c = is64 ? (int)((const long long*)yv)[row] : ((const int*)yv)[row];
        g_cls[row]     = c;
        g_selfsim[row] = sb;
    }
}

// ---------------------------------------------------------------------------
__device__ __forceinline__ void map_tile(int t, int& bi, int& bj) {
    int b = 0, r = t;
    #pragma unroll 1
    while (r >= GI - b) { r -= GI - b; b++; }
    bi = b; bj = b + r;
}

__device__ __forceinline__ void issue_chunk(uint32_t sbase, int buf, int ck,
                                            int iBase, int jBase, int tid) {
    #pragma unroll
    for (int q = 0; q < 4; q++) {
        int s  = tid + q * 256;
        int r  = s >> 3;
        int sg = s & 7;
        uint32_t soff = SW128((uint32_t)(r * 128 + sg * 16));
        cp16(sbase + ACH(buf) + soff, g_Ph + (size_t)(iBase + r) * D + ck * 64 + sg * 8);
        cp16(sbase + BCH(buf) + soff, g_Ph + (size_t)(jBase + r) * D + ck * 64 + sg * 8);
    }
    cp_commit();
}

__device__ __forceinline__ void compute_chunk(uint32_t sbase, int buf,
                                              int m0, int n0, int lrow, int lkoff,
                                              uint32_t acc[4][4][2]) {
    const uint32_t aB = sbase + ACH(buf);
    const uint32_t bB = sbase + BCH(buf);
    #pragma unroll
    for (int ks = 0; ks < 4; ks++) {
        uint32_t afr[4][4], bfr[4][2];
        #pragma unroll
        for (int nf2 = 0; nf2 < 2; nf2++) {
            uint32_t r0, r1, r2, r3;
            uint32_t off = (uint32_t)((n0 + nf2 * 16 + lrow) * 128 + lkoff + ks * 32);
            ldsm4(r0, r1, r2, r3, bB + SW128(off));
            bfr[nf2 * 2 + 0][0] = r0; bfr[nf2 * 2 + 0][1] = r2;
            bfr[nf2 * 2 + 1][0] = r1; bfr[nf2 * 2 + 1][1] = r3;
        }
        #pragma unroll
        for (int mf = 0; mf < 4; mf++) {
            uint32_t off = (uint32_t)((m0 + mf * 16 + lrow) * 128 + lkoff + ks * 32);
            ldsm4(afr[mf][0], afr[mf][1], afr[mf][2], afr[mf][3], aB + SW128(off));
        }
        #pragma unroll
        for (int mf = 0; mf < 4; mf++)
            #pragma unroll
            for (int nf = 0; nf < 4; nf++)
                mma16816h(acc[mf][nf], afr[mf], bfr[nf]);
    }
}

// ---------------------------------------------------------------------------
// k_main: persistent, 3 CTAs/SM, 2-deep cross-tile cp.async ring, f16 MMA
// ---------------------------------------------------------------------------
__global__ void __launch_bounds__(256, 3) k_main() {
    extern __shared__ __align__(128) unsigned char smem[];
    const uint32_t sbase = smem_u32(smem);
    const int tid  = threadIdx.x;
    const int wid  = tid >> 5;
    const int lane = tid & 31;
    const int STR  = gridDim.x;

    int*   clsI  = (int*)(smem + CLSI_OFF);
    int*   clsJ  = (int*)(smem + CLSJ_OFF);
    float* sAccI = (float*)(smem + SACCI_OFF);
    float* sBccI = (float*)(smem + SBCCI_OFF);
    float* sAccJ = (float*)(smem + SACCJ_OFF);
    float* sBccJ = (float*)(smem + SBCCJ_OFF);

    int tile = blockIdx.x;
    if (tile >= NTILES) return;

    int biBlk, bjBlk;
    map_tile(tile, biBlk, bjBlk);
    int iBase = biBlk * TM;
    int jBase = bjBlk * TN;
    bool offdiag = (biBlk != bjBlk);

    if (tid < 128) {
        clsI[tid] = g_cls[iBase + tid];
        sAccI[tid] = 0.0f; sBccI[tid] = 0.0f;
        sAccJ[tid] = 0.0f; sBccJ[tid] = 0.0f;
    } else {
        clsJ[tid - 128] = g_cls[jBase + tid - 128];
    }

    // ---- issue cursor (2 chunk-groups in flight; dummy tail re-issues) ----
    int issTile = tile, issIB = iBase, issJB = jBase, issCk = 0;
    int ibuf = 0, cbuf = 0;
    #pragma unroll
    for (int p = 0; p < 2; p++) {
        issue_chunk(sbase, ibuf, issCk, issIB, issJB, tid);
        ibuf ^= 1;
        if (++issCk == 4) {
            issCk = 0;
            issTile += STR;
            if (issTile < NTILES) {
                int a, b; map_tile(issTile, a, b);
                issIB = a * TM; issJB = b * TN;
            }
        }
    }

    const int m0 = (wid >> 2) * 64;
    const int n0 = (wid & 3) * 32;
    const int lrow  = lane & 15;
    const int lkoff = (lane >> 4) * 16;
    const int gl   = lane >> 2;
    const int quad = lane & 3;

    #pragma unroll 1
    while (true) {
        const int ntile = tile + STR;
        const bool last = (ntile >= NTILES);

        uint32_t acc[4][4][2];
        #pragma unroll
        for (int mf = 0; mf < 4; mf++)
            #pragma unroll
            for (int nf = 0; nf < 4; nf++) { acc[mf][nf][0] = 0u; acc[mf][nf][1] = 0u; }

        #pragma unroll 1
        for (int ck = 0; ck < 4; ck++) {
            asm volatile("cp.async.wait_group 1;" ::: "memory");
            __syncthreads();                       // chunk data visible to all
            compute_chunk(sbase, cbuf, m0, n0, lrow, lkoff, acc);
            __syncthreads();                       // all done reading this buf
            issue_chunk(sbase, cbuf, issCk, issIB, issJB, tid);
            cbuf ^= 1;
            if (++issCk == 4) {
                issCk = 0;
                issTile += STR;
                if (issTile < NTILES) {
                    int a, b; map_tile(issTile, a, b);
                    issIB = a * TM; issJB = b * TN;
                }
            }
        }

        // ---- epilogue: unpack f16 acc, masked exp sums ----
        int cjr[8];
        #pragma unroll
        for (int q = 0; q < 8; q++)
            cjr[q] = clsJ[n0 + (q >> 1) * 8 + quad * 2 + (q & 1)];

        float aCol[8], bCol[8];
        #pragma unroll
        for (int q = 0; q < 8; q++) { aCol[q] = 0.0f; bCol[q] = 0.0f; }

        #pragma unroll
        for (int rr = 0; rr < 2; rr++) {
            #pragma unroll
            for (int mf = 0; mf < 4; mf++) {
                const int rl = m0 + mf * 16 + gl + rr * 8;
                const int ci = clsI[rl];
                float aRow = 0.0f, bRow = 0.0f;
                #pragma unroll
                for (int q = 0; q < 8; q++) {
                    const int nf = q >> 1;
                    float2 pr = __half22float2(*(const __half2*)&acc[mf][nf][rr]);
                    const float s = (q & 1) ? pr.y : pr.x;
                    const bool same = (ci == cjr[q]);
                    const float v = ex2(s * (same ? -EX2SC : EX2SC));
                    const float va = same ? 0.0f : v;
                    const float vb = v - va;
                    aRow += va; bRow += vb;
                    aCol[q] += va; bCol[q] += vb;
                }
                aRow += __shfl_xor_sync(0xffffffffu, aRow, 1);
                aRow += __shfl_xor_sync(0xffffffffu, aRow, 2);
                bRow += __shfl_xor_sync(0xffffffffu, bRow, 1);
                bRow += __shfl_xor_sync(0xffffffffu, bRow, 2);
                if (quad == 0) {
                    atomicAdd(&sAccI[rl], aRow);
                    atomicAdd(&sBccI[rl], bRow);
                }
            }
        }

        if (offdiag) {
            #pragma unroll
            for (int q = 0; q < 8; q++) {
                float a = aCol[q], b = bCol[q];
                #pragma unroll
                for (int o = 4; o <= 16; o <<= 1) {
                    a += __shfl_xor_sync(0xffffffffu, a, o);
                    b += __shfl_xor_sync(0xffffffffu, b, o);
                }
                if (lane < 4) {
                    const int cl = n0 + (q >> 1) * 8 + quad * 2 + (q & 1);
                    atomicAdd(&sAccJ[cl], a);
                    atomicAdd(&sBccJ[cl], b);
                }
            }
        }

        __syncthreads();                            // epilogue smem atomics done

        int nbi = biBlk, nbj = bjBlk;
        if (!last) map_tile(ntile, nbi, nbj);
        const int niBase = nbi * TM;
        const int njBase = nbj * TN;

        if (tid < 128) {
            atomicAdd(&g_A[iBase + tid], sAccI[tid]);
            atomicAdd(&g_B[iBase + tid], sBccI[tid]);
            if (offdiag) {
                atomicAdd(&g_A[jBase + tid], sAccJ[tid]);
                atomicAdd(&g_B[jBase + tid], sBccJ[tid]);
            }
            sAccI[tid] = 0.0f; sBccI[tid] = 0.0f;
            sAccJ[tid] = 0.0f; sBccJ[tid] = 0.0f;
            clsI[tid] = g_cls[niBase + tid];
        } else {
            clsJ[tid - 128] = g_cls[njBase + tid - 128];
        }

        if (last) break;
        tile = ntile; biBlk = nbi; bjBlk = nbj;
        iBase = niBase; jBase = njBase;
        offdiag = (nbi != nbj);
    }
}

// ---------------------------------------------------------------------------
// k_loss: histogram, subtract self term (f16-rounded), empty-set, mean
// ---------------------------------------------------------------------------
__global__ void k_loss(float* __restrict__ out) {
    __shared__ float red[256];
    __shared__ int hist[16];
    const int tid = threadIdx.x;
    if (tid < 16) hist[tid] = 0;
    __syncthreads();
    for (int r = tid; r < N; r += 256) atomicAdd(&hist[g_cls[r] & 15], 1);
    __syncthreads();

    const float MF = __expf(0.5f * INV_T);
    float sum = 0.0f;
    for (int r = tid; r < N; r += 256) {
        int   c   = g_cls[r] & 15;
        int   cnt = hist[c];
        float ssh = __half2float(__float2half_rn(g_selfsim[r]));
        float Bv  = g_B[r] - __expf(-ssh * INV_T);
        float Av  = (N - cnt > 0) ? g_A[r] : 1.0f;
        Bv        = (cnt - 1 > 0) ? Bv : 1.0f;
        sum += log1pf(MF * Av * Bv);
    }
    red[tid] = sum;
    __syncthreads();
    #pragma unroll
    for (int s = 128; s; s >>= 1) {
        if (tid < s) red[tid] += red[tid + s];
        __syncthreads();
    }
    if (tid == 0) out[0] = red[0] / (float)N;
}

// ---------------------------------------------------------------------------
extern "C" void kernel_launch(void* const* d_in, const int* in_sizes, int n_in,
                              void* d_out, int out_size) {
    const float* P = (const float*)d_in[0];
    const void*  y = d_in[1];
    float*     out = (float*)d_out;

    cudaFuncSetAttribute(k_main, cudaFuncAttributeMaxDynamicSharedMemorySize,
                         SMEM_BYTES);

    int sms = 148;
    cudaDeviceGetAttribute(&sms, cudaDevAttrMultiProcessorCount, 0);
    int grid = 3 * sms;
    if (grid > NTILES) grid = NTILES;

    k_norm<<<N / 8, 256>>>(P, y);
    k_main<<<grid, 256, SMEM_BYTES>>>();
    k_loss<<<1, 256>>>(out);
}

// round 15
// speedup vs baseline: 1.0703x; 1.0703x over previous
#include <cuda_runtime.h>
#include <cuda_fp16.h>
#include <math.h>
#include <stdint.h>

#define N    8192
#define D    256
#define INV_T (1.0f / 0.7f)
#define EX2SC (1.44269504088896f * INV_T)   // log2(e)/T  (folded into A operand)

#define TM 128
#define TN 128
#define GI (N / TM)                  // 64
#define NTILES (GI * (GI + 1) / 2)   // 2080

// ---------------- device scratch ----------------
__device__ __half g_Ph[N * D];       // normalized rows, f16           (B side)
__device__ __half g_Pha[N * D];      // normalized rows * EX2SC, f16   (A side)
__device__ float  g_A[N];
__device__ float  g_B[N];
__device__ float  g_selfsim[N];      // scaled self-dot: sum(ha*h) in f32
__device__ int    g_cls[N];
__device__ __half g_clsh[N];

// ---------------- helpers ----------------
__device__ __forceinline__ uint32_t smem_u32(const void* p) {
    uint32_t a;
    asm("{ .reg .u64 t; cvta.to.shared.u64 t, %1; cvt.u32.u64 %0, t; }"
        : "=r"(a) : "l"(p));
    return a;
}
#define SW128(off) ((off) ^ (((off) >> 3) & 0x70))

__device__ __forceinline__ void cp16(uint32_t dst, const void* src) {
    asm volatile("cp.async.cg.shared.global [%0], [%1], 16;" :: "r"(dst), "l"(src));
}
__device__ __forceinline__ void cp_commit() {
    asm volatile("cp.async.commit_group;" ::: "memory");
}
__device__ __forceinline__ void ldsm4(uint32_t& r0, uint32_t& r1,
                                      uint32_t& r2, uint32_t& r3, uint32_t addr) {
    asm volatile("ldmatrix.sync.aligned.m8n8.x4.shared.b16 {%0,%1,%2,%3}, [%4];"
                 : "=r"(r0), "=r"(r1), "=r"(r2), "=r"(r3) : "r"(addr));
}
__device__ __forceinline__ void mma16816h(uint32_t* d, const uint32_t* a,
                                          const uint32_t* b) {
    asm volatile("mma.sync.aligned.m16n8k16.row.col.f16.f16.f16.f16 "
                 "{%0,%1}, {%2,%3,%4,%5}, {%6,%7}, {%0,%1};"
                 : "+r"(d[0]), "+r"(d[1])
                 : "r"(a[0]), "r"(a[1]), "r"(a[2]), "r"(a[3]),
                   "r"(b[0]), "r"(b[1]));
}
__device__ __forceinline__ __half2 h2ex2(__half2 x) {
    uint32_t r, xi = *(uint32_t*)&x;
    asm("ex2.approx.f16x2 %0, %1;" : "=r"(r) : "r"(xi));
    return *(__half2*)&r;
}

// ---------------- SMEM layout: 3-deep ring of (A16KB + B16KB) chunks --------
#define ACH(b) ((b) * 16384)
#define BCH(b) (49152 + (b) * 16384)
#define CLSIH_OFF 98304                      // 128 half
#define CLSJH_OFF 98560                      // 128 half
#define SACCI_OFF 98816
#define SBCCI_OFF 99328
#define SACCJ_OFF 99840
#define SBCCJ_OFF 100352
#define SMEM_BYTES 100864                    // x2 CTAs/SM

// ---------------------------------------------------------------------------
// k_norm: detect + zero A/B + normalize -> f16 (plain + scaled) + selfsim + cls
// ---------------------------------------------------------------------------
__global__ void k_norm(const float* __restrict__ P, const void* __restrict__ yv) {
    __shared__ int s_is64;
    const int tid  = threadIdx.x;
    const int w    = tid >> 5;
    const int lane = tid & 31;
    const int row  = blockIdx.x * 8 + w;

    if (w == 0) {
        int v = ((const int*)yv)[2 * lane + 1];
        unsigned any = __ballot_sync(0xffffffffu, v != 0);
        if (lane == 0) s_is64 = (any == 0) ? 1 : 0;
    }
    if (blockIdx.x < 32) {
        int idx = blockIdx.x * 256 + tid;
        g_A[idx] = 0.0f; g_B[idx] = 0.0f;
    }
    __syncthreads();
    const int is64 = s_is64;

    const float4* p4 = (const float4*)(P + (size_t)row * D);
    float4 v0 = p4[lane];
    float4 v1 = p4[lane + 32];

    float ss = v0.x*v0.x + v0.y*v0.y + v0.z*v0.z + v0.w*v0.w
             + v1.x*v1.x + v1.y*v1.y + v1.z*v1.z + v1.w*v1.w;
    #pragma unroll
    for (int o = 16; o; o >>= 1) ss += __shfl_xor_sync(0xffffffffu, ss, o);
    float rn = rsqrtf(ss);

    float f[8] = {v0.x, v0.y, v0.z, v0.w, v1.x, v1.y, v1.z, v1.w};
    __half h[8], ha[8];
    float sb = 0.0f;
    #pragma unroll
    for (int q = 0; q < 8; q++) {
        float fn = f[q] * rn;
        h[q]  = __float2half_rn(fn);
        ha[q] = __float2half_rn(fn * EX2SC);
        sb += __half2float(h[q]) * __half2float(ha[q]);
    }
    #pragma unroll
    for (int o = 16; o; o >>= 1) sb += __shfl_xor_sync(0xffffffffu, sb, o);

    *(uint2*)(g_Ph  + (size_t)row * D + lane * 4)       = *(uint2*)&h[0];
    *(uint2*)(g_Ph  + (size_t)row * D + 128 + lane * 4) = *(uint2*)&h[4];
    *(uint2*)(g_Pha + (size_t)row * D + lane * 4)       = *(uint2*)&ha[0];
    *(uint2*)(g_Pha + (size_t)row * D + 128 + lane * 4) = *(uint2*)&ha[4];

    if (lane == 0) {
        int c = is64 ? (int)((const long long*)yv)[row] : ((const int*)yv)[row];
        g_cls[row]     = c;
        g_clsh[row]    = __float2half_rn((float)c);
        g_selfsim[row] = sb;
    }
}

// ---------------------------------------------------------------------------
__device__ __forceinline__ void map_tile(int t, int& bi, int& bj) {
    int b = 0, r = t;
    #pragma unroll 1
    while (r >= GI - b) { r -= GI - b; b++; }
    bi = b; bj = b + r;
}

__device__ __forceinline__ void issue_chunk(uint32_t sbase, int buf, int ck,
                                            int iBase, int jBase, int tid) {
    #pragma unroll
    for (int q = 0; q < 4; q++) {
        int s  = tid + q * 256;
        int r  = s >> 3;
        int sg = s & 7;
        uint32_t soff = SW128((uint32_t)(r * 128 + sg * 16));
        cp16(sbase + ACH(buf) + soff, g_Pha + (size_t)(iBase + r) * D + ck * 64 + sg * 8);
        cp16(sbase + BCH(buf) + soff, g_Ph  + (size_t)(jBase + r) * D + ck * 64 + sg * 8);
    }
    cp_commit();
}

__device__ __forceinline__ void compute_chunk(uint32_t sbase, int buf,
                                              int m0, int n0, int lrow, int lkoff,
                                              uint32_t acc[4][4][2]) {
    const uint32_t aB = sbase + ACH(buf);
    const uint32_t bB = sbase + BCH(buf);
    #pragma unroll
    for (int ks = 0; ks < 4; ks++) {
        uint32_t afr[4][4], bfr[4][2];
        #pragma unroll
        for (int nf2 = 0; nf2 < 2; nf2++) {
            uint32_t r0, r1, r2, r3;
            uint32_t off = (uint32_t)((n0 + nf2 * 16 + lrow) * 128 + lkoff + ks * 32);
            ldsm4(r0, r1, r2, r3, bB + SW128(off));
            bfr[nf2 * 2 + 0][0] = r0; bfr[nf2 * 2 + 0][1] = r2;
            bfr[nf2 * 2 + 1][0] = r1; bfr[nf2 * 2 + 1][1] = r3;
        }
        #pragma unroll
        for (int mf = 0; mf < 4; mf++) {
            uint32_t off = (uint32_t)((m0 + mf * 16 + lrow) * 128 + lkoff + ks * 32);
            ldsm4(afr[mf][0], afr[mf][1], afr[mf][2], afr[mf][3], aB + SW128(off));
        }
        #pragma unroll
        for (int mf = 0; mf < 4; mf++)
            #pragma unroll
            for (int nf = 0; nf < 4; nf++)
                mma16816h(acc[mf][nf], afr[mf], bfr[nf]);
    }
}

// ---------------------------------------------------------------------------
// k_main: persistent, 2 CTAs/SM, 3-deep cross-tile cp.async ring, f16 MMA,
// packed-f16 epilogue (acc already = s*log2(e)/T via scaled A operand).
// ---------------------------------------------------------------------------
__global__ void __launch_bounds__(256, 2) k_main() {
    extern __shared__ __align__(128) unsigned char smem[];
    const uint32_t sbase = smem_u32(smem);
    const int tid  = threadIdx.x;
    const int wid  = tid >> 5;
    const int lane = tid & 31;
    const int STR  = gridDim.x;

    __half*  clsIh = (__half*)(smem + CLSIH_OFF);
    __half*  clsJh = (__half*)(smem + CLSJH_OFF);
    float*   sAccI = (float*)(smem + SACCI_OFF);
    float*   sBccI = (float*)(smem + SBCCI_OFF);
    float*   sAccJ = (float*)(smem + SACCJ_OFF);
    float*   sBccJ = (float*)(smem + SBCCJ_OFF);

    int tile = blockIdx.x;
    if (tile >= NTILES) return;

    int biBlk, bjBlk;
    map_tile(tile, biBlk, bjBlk);
    int iBase = biBlk * TM;
    int jBase = bjBlk * TN;
    bool offdiag = (biBlk != bjBlk);

    if (tid < 128) {
        clsIh[tid] = g_clsh[iBase + tid];
        sAccI[tid] = 0.0f; sBccI[tid] = 0.0f;
        sAccJ[tid] = 0.0f; sBccJ[tid] = 0.0f;
    } else {
        clsJh[tid - 128] = g_clsh[jBase + tid - 128];
    }

    // ---- issue cursor: 3 chunk-groups in flight ----
    int issTile = tile, issIB = iBase, issJB = jBase, issCk = 0;
    int buf = 0;
    #pragma unroll
    for (int p = 0; p < 3; p++) {
        issue_chunk(sbase, p, issCk, issIB, issJB, tid);
        if (++issCk == 4) {
            issCk = 0;
            issTile += STR;
            if (issTile < NTILES) {
                int a, b; map_tile(issTile, a, b);
                issIB = a * TM; issJB = b * TN;
            }
        }
    }

    const int m0 = (wid >> 2) * 64;
    const int n0 = (wid & 3) * 32;
    const int lrow  = lane & 15;
    const int lkoff = (lane >> 4) * 16;
    const int gl   = lane >> 2;
    const int quad = lane & 3;

    const __half2 ONE2  = __float2half2_rn(1.0f);
    const __half2 MTWO2 = __float2half2_rn(-2.0f);

    #pragma unroll 1
    while (true) {
        const int ntile = tile + STR;
        const bool last = (ntile >= NTILES);

        uint32_t acc[4][4][2];
        #pragma unroll
        for (int mf = 0; mf < 4; mf++)
            #pragma unroll
            for (int nf = 0; nf < 4; nf++) { acc[mf][nf][0] = 0u; acc[mf][nf][1] = 0u; }

        #pragma unroll 1
        for (int ck = 0; ck < 4; ck++) {
            asm volatile("cp.async.wait_group 2;" ::: "memory");
            __syncthreads();
            compute_chunk(sbase, buf, m0, n0, lrow, lkoff, acc);
            __syncthreads();
            issue_chunk(sbase, buf, issCk, issIB, issJB, tid);
            buf = (buf == 2) ? 0 : buf + 1;
            if (++issCk == 4) {
                issCk = 0;
                issTile += STR;
                if (issTile < NTILES) {
                    int a, b; map_tile(issTile, a, b);
                    issIB = a * TM; issJB = b * TN;
                }
            }
        }

        // ---- packed-f16 epilogue ----
        __half2 cjh[4];
        #pragma unroll
        for (int nf = 0; nf < 4; nf++)
            cjh[nf] = ((const __half2*)clsJh)[(n0 >> 1) + nf * 4 + quad];

        __half2 aColH[4], bColH[4];
        #pragma unroll
        for (int nf = 0; nf < 4; nf++) {
            aColH[nf] = __float2half2_rn(0.0f);
            bColH[nf] = __float2half2_rn(0.0f);
        }

        #pragma unroll
        for (int rr = 0; rr < 2; rr++) {
            #pragma unroll
            for (int mf = 0; mf < 4; mf++) {
                const int rl = m0 + mf * 16 + gl + rr * 8;
                const __half2 cih2 = __half2half2(clsIh[rl]);
                __half2 aRowH = __float2half2_rn(0.0f);
                __half2 bRowH = __float2half2_rn(0.0f);
                #pragma unroll
                for (int nf = 0; nf < 4; nf++) {
                    __half2 s2 = *(const __half2*)&acc[mf][nf][rr];
                    __half2 m  = __heq2(cih2, cjh[nf]);       // 1 where same class
                    __half2 sc = __hfma2(m, MTWO2, ONE2);     // +1 diff, -1 same
                    __half2 v  = h2ex2(__hmul2(s2, sc));      // 2^{±s*EX2SC}
                    __half2 vb = __hmul2(v, m);               // same-class part
                    __half2 va = __hsub2(v, vb);              // diff-class part
                    aRowH = __hadd2(aRowH, va);
                    bRowH = __hadd2(bRowH, vb);
                    aColH[nf] = __hadd2(aColH[nf], va);
                    bColH[nf] = __hadd2(bColH[nf], vb);
                }
                float2 fa = __half22float2(aRowH);
                float2 fb = __half22float2(bRowH);
                float aRow = fa.x + fa.y;
                float bRow = fb.x + fb.y;
                aRow += __shfl_xor_sync(0xffffffffu, aRow, 1);
                aRow += __shfl_xor_sync(0xffffffffu, aRow, 2);
                bRow += __shfl_xor_sync(0xffffffffu, bRow, 1);
                bRow += __shfl_xor_sync(0xffffffffu, bRow, 2);
                if (quad == 0) {
                    atomicAdd(&sAccI[rl], aRow);
                    atomicAdd(&sBccI[rl], bRow);
                }
            }
        }

        if (offdiag) {
            #pragma unroll
            for (int nf = 0; nf < 4; nf++) {
                uint32_t a = *(uint32_t*)&aColH[nf];
                uint32_t b = *(uint32_t*)&bColH[nf];
                #pragma unroll
                for (int o = 4; o <= 16; o <<= 1) {
                    uint32_t ax = __shfl_xor_sync(0xffffffffu, a, o);
                    uint32_t bx = __shfl_xor_sync(0xffffffffu, b, o);
                    *( __half2*)&a = __hadd2(*(__half2*)&a, *(__half2*)&ax);
                    *( __half2*)&b = __hadd2(*(__half2*)&b, *(__half2*)&bx);
                }
                if (lane < 4) {
                    const int cl = n0 + nf * 8 + quad * 2;
                    float2 fa = __half22float2(*(__half2*)&a);
                    float2 fb = __half22float2(*(__half2*)&b);
                    atomicAdd(&sAccJ[cl],     fa.x);
                    atomicAdd(&sAccJ[cl + 1], fa.y);
                    atomicAdd(&sBccJ[cl],     fb.x);
                    atomicAdd(&sBccJ[cl + 1], fb.y);
                }
            }
        }

        __syncthreads();

        int nbi = biBlk, nbj = bjBlk;
        if (!last) map_tile(ntile, nbi, nbj);
        const int niBase = nbi * TM;
        const int njBase = nbj * TN;

        if (tid < 128) {
            atomicAdd(&g_A[iBase + tid], sAccI[tid]);
            atomicAdd(&g_B[iBase + tid], sBccI[tid]);
            if (offdiag) {
                atomicAdd(&g_A[jBase + tid], sAccJ[tid]);
                atomicAdd(&g_B[jBase + tid], sBccJ[tid]);
            }
            sAccI[tid] = 0.0f; sBccI[tid] = 0.0f;
            sAccJ[tid] = 0.0f; sBccJ[tid] = 0.0f;
            clsIh[tid] = g_clsh[niBase + tid];
        } else {
            clsJh[tid - 128] = g_clsh[njBase + tid - 128];
        }

        if (last) break;
        tile = ntile; biBlk = nbi; bjBlk = nbj;
        iBase = niBase; jBase = njBase;
        offdiag = (nbi != nbj);
    }
}

// ---------------------------------------------------------------------------
// k_loss: histogram, subtract self term (scaled space), empty-set, mean
// ---------------------------------------------------------------------------
__global__ void k_loss(float* __restrict__ out) {
    __shared__ float red[256];
    __shared__ int hist[16];
    const int tid = threadIdx.x;
    if (tid < 16) hist[tid] = 0;
    __syncthreads();
    for (int r = tid; r < N; r += 256) atomicAdd(&hist[g_cls[r] & 15], 1);
    __syncthreads();

    const float MF = __expf(0.5f * INV_T);
    float sum = 0.0f;
    for (int r = tid; r < N; r += 256) {
        int   c   = g_cls[r] & 15;
        int   cnt = hist[c];
        // self term as the f16 pipeline computed it (argument f16-rounded)
        float ssh = __half2float(__float2half_rn(g_selfsim[r]));
        float Bv  = g_B[r] - exp2f(-ssh);
        float Av  = (N - cnt > 0) ? g_A[r] : 1.0f;
        Bv        = (cnt - 1 > 0) ? Bv : 1.0f;
        sum += log1pf(MF * Av * Bv);
    }
    red[tid] = sum;
    __syncthreads();
    #pragma unroll
    for (int s = 128; s; s >>= 1) {
        if (tid < s) red[tid] += red[tid + s];
        __syncthreads();
    }
    if (tid == 0) out[0] = red[0] / (float)N;
}

// ---------------------------------------------------------------------------
extern "C" void kernel_launch(void* const* d_in, const int* in_sizes, int n_in,
                              void* d_out, int out_size) {
    const float* P = (const float*)d_in[0];
    const void*  y = d_in[1];
    float*     out = (float*)d_out;

    cudaFuncSetAttribute(k_main, cudaFuncAttributeMaxDynamicSharedMemorySize,
                         SMEM_BYTES);

    int sms = 148;
    cudaDeviceGetAttribute(&sms, cudaDevAttrMultiProcessorCount, 0);
    int grid = 2 * sms;
    if (grid > NTILES) grid = NTILES;

    k_norm<<<N / 8, 256>>>(P, y);
    k_main<<<grid, 256, SMEM_BYTES>>>();
    k_loss<<<1, 256>>>(out);
}

// round 16
// speedup vs baseline: 1.1058x; 1.0332x over previous
#include <cuda_runtime.h>
#include <cuda_fp16.h>
#include <math.h>
#include <stdint.h>

#define N    8192
#define D    256
#define INV_T (1.0f / 0.7f)
#define SQS  1.43561585f              // sqrt(log2(e)/T): folded into BOTH operands

#define TM 128
#define TNP 256                       // j-pair width
#define GI (N / TM)                   // 64
#define NSUP 1056                     // supertiles: sum_{b=0}^{31} (2b+2)

// ---------------- device scratch ----------------
__device__ __half g_Phs[N * D];       // normalized rows * sqrt(EX2SC), f16
__device__ float  g_A[N];
__device__ float  g_B[N];
__device__ float  g_selfsim[N];       // scaled self-dot (f32)
__device__ int    g_cls[N];
__device__ __half g_clsh[N];

// ---------------- helpers ----------------
__device__ __forceinline__ uint32_t smem_u32(const void* p) {
    uint32_t a;
    asm("{ .reg .u64 t; cvta.to.shared.u64 t, %1; cvt.u32.u64 %0, t; }"
        : "=r"(a) : "l"(p));
    return a;
}
#define SW128(off) ((off) ^ (((off) >> 3) & 0x70))

__device__ __forceinline__ void cp16(uint32_t dst, const void* src) {
    asm volatile("cp.async.cg.shared.global [%0], [%1], 16;" :: "r"(dst), "l"(src));
}
__device__ __forceinline__ void cp_commit() {
    asm volatile("cp.async.commit_group;" ::: "memory");
}
__device__ __forceinline__ void ldsm4(uint32_t& r0, uint32_t& r1,
                                      uint32_t& r2, uint32_t& r3, uint32_t addr) {
    asm volatile("ldmatrix.sync.aligned.m8n8.x4.shared.b16 {%0,%1,%2,%3}, [%4];"
                 : "=r"(r0), "=r"(r1), "=r"(r2), "=r"(r3) : "r"(addr));
}
__device__ __forceinline__ void mma16816h(uint32_t* d, const uint32_t* a,
                                          const uint32_t* b) {
    asm volatile("mma.sync.aligned.m16n8k16.row.col.f16.f16.f16.f16 "
                 "{%0,%1}, {%2,%3,%4,%5}, {%6,%7}, {%0,%1};"
                 : "+r"(d[0]), "+r"(d[1])
                 : "r"(a[0]), "r"(a[1]), "r"(a[2]), "r"(a[3]),
                   "r"(b[0]), "r"(b[1]));
}
__device__ __forceinline__ __half2 h2ex2(__half2 x) {
    uint32_t r, xi = *(uint32_t*)&x;
    asm("ex2.approx.f16x2 %0, %1;" : "=r"(r) : "r"(xi));
    return *(__half2*)&r;
}

// ---------------- SMEM: 2-deep ring, chunk = A(128x128B) + B(256x128B) ------
#define ACH(b) ((b) * 16384)                 // A bufs @ 0, 16384
#define BCH(b) (32768 + (b) * 32768)         // B bufs @ 32768, 65536
#define CLSIH_OFF 98304                      // 128 half
#define CLSJH_OFF 98560                      // 256 half
#define SACCI_OFF 99072                      // 128 f32
#define SBCCI_OFF 99584
#define SACCJ_OFF 100096                     // 256 f32
#define SBCCJ_OFF 101120
#define SMEM_BYTES 102144                    // x2 CTAs = 204288 B/SM

// ---------------------------------------------------------------------------
// k_norm: detect + zero A/B + normalize -> f16*sqrt(EX2SC) + selfsim + cls
// ---------------------------------------------------------------------------
__global__ void k_norm(const float* __restrict__ P, const void* __restrict__ yv) {
    __shared__ int s_is64;
    const int tid  = threadIdx.x;
    const int w    = tid >> 5;
    const int lane = tid & 31;
    const int row  = blockIdx.x * 8 + w;

    if (w == 0) {
        int v = ((const int*)yv)[2 * lane + 1];
        unsigned any = __ballot_sync(0xffffffffu, v != 0);
        if (lane == 0) s_is64 = (any == 0) ? 1 : 0;
    }
    if (blockIdx.x < 32) {
        int idx = blockIdx.x * 256 + tid;
        g_A[idx] = 0.0f; g_B[idx] = 0.0f;
    }
    __syncthreads();
    const int is64 = s_is64;

    const float4* p4 = (const float4*)(P + (size_t)row * D);
    float4 v0 = p4[lane];
    float4 v1 = p4[lane + 32];

    float ss = v0.x*v0.x + v0.y*v0.y + v0.z*v0.z + v0.w*v0.w
             + v1.x*v1.x + v1.y*v1.y + v1.z*v1.z + v1.w*v1.w;
    #pragma unroll
    for (int o = 16; o; o >>= 1) ss += __shfl_xor_sync(0xffffffffu, ss, o);
    float rq = rsqrtf(ss) * SQS;

    float f[8] = {v0.x, v0.y, v0.z, v0.w, v1.x, v1.y, v1.z, v1.w};
    __half h[8];
    float sb = 0.0f;
    #pragma unroll
    for (int q = 0; q < 8; q++) {
        h[q] = __float2half_rn(f[q] * rq);
        float hf = __half2float(h[q]);
        sb += hf * hf;
    }
    #pragma unroll
    for (int o = 16; o; o >>= 1) sb += __shfl_xor_sync(0xffffffffu, sb, o);

    *(uint2*)(g_Phs + (size_t)row * D + lane * 4)       = *(uint2*)&h[0];
    *(uint2*)(g_Phs + (size_t)row * D + 128 + lane * 4) = *(uint2*)&h[4];

    if (lane == 0) {
        int c = is64 ? (int)((const long long*)yv)[row] : ((const int*)yv)[row];
        g_cls[row]     = c;
        g_clsh[row]    = __float2half_rn((float)c);
        g_selfsim[row] = sb;
    }
}

// ---------------------------------------------------------------------------
// supertile s -> (bi, bjp): for bjp, bi in [0, 2*bjp+1]
__device__ __forceinline__ void map_sup(int s, int& bi, int& bjp) {
    int b = 0, r = s;
    #pragma unroll 1
    while (r >= 2 * b + 2) { r -= 2 * b + 2; b++; }
    bjp = b; bi = r;
}

__device__ __forceinline__ void issue_chunk(uint32_t sbase, int buf, int ck,
                                            int iBase, int jBase, int tid) {
    // A: 128 rows x 8 segs = 1024 cp16
    #pragma unroll
    for (int q = 0; q < 4; q++) {
        int s  = tid + q * 256;
        int r  = s >> 3;
        int sg = s & 7;
        uint32_t soff = SW128((uint32_t)(r * 128 + sg * 16));
        cp16(sbase + ACH(buf) + soff, g_Phs + (size_t)(iBase + r) * D + ck * 64 + sg * 8);
    }
    // B: 256 rows x 8 segs = 2048 cp16
    #pragma unroll
    for (int q = 0; q < 8; q++) {
        int s  = tid + q * 256;
        int r  = s >> 3;
        int sg = s & 7;
        uint32_t soff = SW128((uint32_t)(r * 128 + sg * 16));
        cp16(sbase + BCH(buf) + soff, g_Phs + (size_t)(jBase + r) * D + ck * 64 + sg * 8);
    }
    cp_commit();
}

__device__ __forceinline__ void compute_chunk(uint32_t sbase, int buf,
                                              int m0, int n0, int lrow, int lkoff,
                                              uint32_t acc[4][8][2]) {
    const uint32_t aB = sbase + ACH(buf);
    const uint32_t bB = sbase + BCH(buf);
    #pragma unroll
    for (int ks = 0; ks < 4; ks++) {
        uint32_t afr[4][4], bfr[8][2];
        #pragma unroll
        for (int nf2 = 0; nf2 < 4; nf2++) {
            uint32_t r0, r1, r2, r3;
            uint32_t off = (uint32_t)((n0 + nf2 * 16 + lrow) * 128 + lkoff + ks * 32);
            ldsm4(r0, r1, r2, r3, bB + SW128(off));
            bfr[nf2 * 2 + 0][0] = r0; bfr[nf2 * 2 + 0][1] = r2;
            bfr[nf2 * 2 + 1][0] = r1; bfr[nf2 * 2 + 1][1] = r3;
        }
        #pragma unroll
        for (int mf = 0; mf < 4; mf++) {
            uint32_t off = (uint32_t)((m0 + mf * 16 + lrow) * 128 + lkoff + ks * 32);
            ldsm4(afr[mf][0], afr[mf][1], afr[mf][2], afr[mf][3], aB + SW128(off));
        }
        #pragma unroll
        for (int mf = 0; mf < 4; mf++)
            #pragma unroll
            for (int nf = 0; nf < 8; nf++)
                mma16816h(acc[mf][nf], afr[mf], bfr[nf]);
    }
}

// ---------------------------------------------------------------------------
// k_main: persistent, 2 CTAs/SM, 128x256 supertiles (64x64 warp tiles),
// 2-deep ring, packed-f16 epilogue
// ---------------------------------------------------------------------------
__global__ void __launch_bounds__(256, 2) k_main() {
    extern __shared__ __align__(128) unsigned char smem[];
    const uint32_t sbase = smem_u32(smem);
    const int tid  = threadIdx.x;
    const int wid  = tid >> 5;
    const int lane = tid & 31;
    const int STR  = gridDim.x;

    __half* clsIh = (__half*)(smem + CLSIH_OFF);
    __half* clsJh = (__half*)(smem + CLSJH_OFF);
    float*  sAccI = (float*)(smem + SACCI_OFF);
    float*  sBccI = (float*)(smem + SBCCI_OFF);
    float*  sAccJ = (float*)(smem + SACCJ_OFF);
    float*  sBccJ = (float*)(smem + SBCCJ_OFF);

    int sup = blockIdx.x;
    if (sup >= NSUP) return;

    int bi, bjp;
    map_sup(sup, bi, bjp);
    int iBase = bi * TM;
    int jBase = bjp * TNP;

    if (tid < 128) {
        clsIh[tid] = g_clsh[iBase + tid];
        sAccI[tid] = 0.0f; sBccI[tid] = 0.0f;
    }
    clsJh[tid] = g_clsh[jBase + tid];
    sAccJ[tid] = 0.0f; sBccJ[tid] = 0.0f;

    // ---- issue cursor: 2 chunk-groups in flight ----
    int issSup = sup, issIB = iBase, issJB = jBase, issCk = 0;
    #pragma unroll
    for (int p = 0; p < 2; p++) {
        issue_chunk(sbase, p, issCk, issIB, issJB, tid);
        if (++issCk == 4) {
            issCk = 0;
            issSup += STR;
            if (issSup < NSUP) {
                int a, b; map_sup(issSup, a, b);
                issIB = a * TM; issJB = b * TNP;
            }
        }
    }

    const int m0 = (wid >> 2) * 64;
    const int n0 = (wid & 3) * 64;
    const int lrow  = lane & 15;
    const int lkoff = (lane >> 4) * 16;
    const int gl   = lane >> 2;
    const int quad = lane & 3;

    const __half2 ONE2  = __float2half2_rn(1.0f);
    const __half2 MTWO2 = __float2half2_rn(-2.0f);

    #pragma unroll 1
    while (true) {
        const int nsup = sup + STR;
        const bool last = (nsup >= NSUP);

        const bool skipLeft = (bi == 2 * bjp + 1);
        const bool epiOn    = !(skipLeft && n0 < 128);
        const bool offdHalf = (n0 < 128) ? (bi != 2 * bjp) : (bi != 2 * bjp + 1);

        uint32_t acc[4][8][2];
        #pragma unroll
        for (int mf = 0; mf < 4; mf++)
            #pragma unroll
            for (int nf = 0; nf < 8; nf++) { acc[mf][nf][0] = 0u; acc[mf][nf][1] = 0u; }

        #pragma unroll 1
        for (int ck = 0; ck < 4; ck++) {
            asm volatile("cp.async.wait_group 1;" ::: "memory");
            __syncthreads();
            compute_chunk(sbase, ck & 1, m0, n0, lrow, lkoff, acc);
            __syncthreads();
            issue_chunk(sbase, ck & 1, issCk, issIB, issJB, tid);
            if (++issCk == 4) {
                issCk = 0;
                issSup += STR;
                if (issSup < NSUP) {
                    int a, b; map_sup(issSup, a, b);
                    issIB = a * TM; issJB = b * TNP;
                }
            }
        }

        // ---- packed-f16 epilogue ----
        __half2 cjh[8];
        #pragma unroll
        for (int nf = 0; nf < 8; nf++)
            cjh[nf] = ((const __half2*)clsJh)[(n0 >> 1) + nf * 4 + quad];

        __half2 aColH[8], bColH[8];
        #pragma unroll
        for (int nf = 0; nf < 8; nf++) {
            aColH[nf] = __float2half2_rn(0.0f);
            bColH[nf] = __float2half2_rn(0.0f);
        }

        #pragma unroll
        for (int rr = 0; rr < 2; rr++) {
            #pragma unroll
            for (int mf = 0; mf < 4; mf++) {
                const int rl = m0 + mf * 16 + gl + rr * 8;
                const __half2 cih2 = __half2half2(clsIh[rl]);
                __half2 aRowH = __float2half2_rn(0.0f);
                __half2 bRowH = __float2half2_rn(0.0f);
                #pragma unroll
                for (int nf = 0; nf < 8; nf++) {
                    __half2 s2 = *(const __half2*)&acc[mf][nf][rr];
                    __half2 m  = __heq2(cih2, cjh[nf]);
                    __half2 sc = __hfma2(m, MTWO2, ONE2);
                    __half2 v  = h2ex2(__hmul2(s2, sc));
                    __half2 vb = __hmul2(v, m);
                    __half2 va = __hsub2(v, vb);
                    aRowH = __hadd2(aRowH, va);
                    bRowH = __hadd2(bRowH, vb);
                    aColH[nf] = __hadd2(aColH[nf], va);
                    bColH[nf] = __hadd2(bColH[nf], vb);
                }
                float2 fa = __half22float2(aRowH);
                float2 fb = __half22float2(bRowH);
                float aRow = fa.x + fa.y;
                float bRow = fb.x + fb.y;
                aRow += __shfl_xor_sync(0xffffffffu, aRow, 1);
                aRow += __shfl_xor_sync(0xffffffffu, aRow, 2);
                bRow += __shfl_xor_sync(0xffffffffu, bRow, 1);
                bRow += __shfl_xor_sync(0xffffffffu, bRow, 2);
                if (epiOn && quad == 0) {
                    atomicAdd(&sAccI[rl], aRow);
                    atomicAdd(&sBccI[rl], bRow);
                }
            }
        }

        if (epiOn && offdHalf) {
            #pragma unroll
            for (int nf = 0; nf < 8; nf++) {
                uint32_t a = *(uint32_t*)&aColH[nf];
                uint32_t b = *(uint32_t*)&bColH[nf];
                #pragma unroll
                for (int o = 4; o <= 16; o <<= 1) {
                    uint32_t ax = __shfl_xor_sync(0xffffffffu, a, o);
                    uint32_t bx = __shfl_xor_sync(0xffffffffu, b, o);
                    *( __half2*)&a = __hadd2(*(__half2*)&a, *(__half2*)&ax);
                    *( __half2*)&b = __hadd2(*(__half2*)&b, *(__half2*)&bx);
                }
                if (lane < 4) {
                    const int cl = n0 + nf * 8 + quad * 2;
                    float2 fa = __half22float2(*(__half2*)&a);
                    float2 fb = __half22float2(*(__half2*)&b);
                    atomicAdd(&sAccJ[cl],     fa.x);
                    atomicAdd(&sAccJ[cl + 1], fa.y);
                    atomicAdd(&sBccJ[cl],     fb.x);
                    atomicAdd(&sBccJ[cl + 1], fb.y);
                }
            }
        }

        __syncthreads();

        int nbi = bi, nbjp = bjp;
        if (!last) map_sup(nsup, nbi, nbjp);
        const int niBase = nbi * TM;
        const int njBase = nbjp * TNP;

        if (tid < 128) {
            atomicAdd(&g_A[iBase + tid], sAccI[tid]);
            atomicAdd(&g_B[iBase + tid], sBccI[tid]);
            sAccI[tid] = 0.0f; sBccI[tid] = 0.0f;
            clsIh[tid] = g_clsh[niBase + tid];
        }
        atomicAdd(&g_A[jBase + tid], sAccJ[tid]);
        atomicAdd(&g_B[jBase + tid], sBccJ[tid]);
        sAccJ[tid] = 0.0f; sBccJ[tid] = 0.0f;
        clsJh[tid] = g_clsh[njBase + tid];

        if (last) break;
        sup = nsup; bi = nbi; bjp = nbjp;
        iBase = niBase; jBase = njBase;
    }
}

// ---------------------------------------------------------------------------
// k_loss: histogram, subtract self term (scaled space), empty-set, mean
// ---------------------------------------------------------------------------
__global__ void k_loss(float* __restrict__ out) {
    __shared__ float red[256];
    __shared__ int hist[16];
    const int tid = threadIdx.x;
    if (tid < 16) hist[tid] = 0;
    __syncthreads();
    for (int r = tid; r < N; r += 256) atomicAdd(&hist[g_cls[r] & 15], 1);
    __syncthreads();

    const float MF = __expf(0.5f * INV_T);
    float sum = 0.0f;
    for (int r = tid; r < N; r += 256) {
        int   c   = g_cls[r] & 15;
        int   cnt = hist[c];
        float ssh = __half2float(__float2half_rn(g_selfsim[r]));
        float Bv  = g_B[r] - exp2f(-ssh);
        float Av  = (N - cnt > 0) ? g_A[r] : 1.0f;
        Bv        = (cnt - 1 > 0) ? Bv : 1.0f;
        sum += log1pf(MF * Av * Bv);
    }
    red[tid] = sum;
    __syncthreads();
    #pragma unroll
    for (int s = 128; s; s >>= 1) {
        if (tid < s) red[tid] += red[tid + s];
        __syncthreads();
    }
    if (tid == 0) out[0] = red[0] / (float)N;
}

// ---------------------------------------------------------------------------
extern "C" void kernel_launch(void* const* d_in, const int* in_sizes, int n_in,
                              void* d_out, int out_size) {
    const float* P = (const float*)d_in[0];
    const void*  y = d_in[1];
    float*     out = (float*)d_out;

    cudaFuncSetAttribute(k_main, cudaFuncAttributeMaxDynamicSharedMemorySize,
                         SMEM_BYTES);

    int sms = 148;
    cudaDeviceGetAttribute(&sms, cudaDevAttrMultiProcessorCount, 0);
    int grid = 2 * sms;
    if (grid > NSUP) grid = NSUP;

    k_norm<<<N / 8, 256>>>(P, y);
    k_main<<<grid, 256, SMEM_BYTES>>>();
    k_loss<<<1, 256>>>(out);
}

// round 17
// speedup vs baseline: 1.1486x; 1.0387x over previous
#include <cuda_runtime.h>
#include <cuda_fp16.h>
#include <math.h>
#include <stdint.h>

#define N    8192
#define D    256
#define INV_T (1.0f / 0.7f)
#define SQS  1.43561585f              // sqrt(log2(e)/T): folded into BOTH operands

#define TM 128
#define TNP 256                       // j-pair width
#define GI (N / TM)                   // 64
#define NSUP 1056                     // supertiles: sum_{b=0}^{31} (2b+2)

// ---------------- device scratch ----------------
__device__ __half g_Phs[N * D];       // normalized rows * sqrt(EX2SC), f16
__device__ float  g_A[N];
__device__ float  g_B[N];
__device__ float  g_selfsim[N];       // scaled self-dot (f32)
__device__ int    g_cls[N];
__device__ __half g_clsh[N];

// ---------------- helpers ----------------
__device__ __forceinline__ uint32_t smem_u32(const void* p) {
    uint32_t a;
    asm("{ .reg .u64 t; cvta.to.shared.u64 t, %1; cvt.u32.u64 %0, t; }"
        : "=r"(a) : "l"(p));
    return a;
}
#define SW128(off) ((off) ^ (((off) >> 3) & 0x70))

__device__ __forceinline__ void cp16(uint32_t dst, const void* src) {
    asm volatile("cp.async.cg.shared.global [%0], [%1], 16;" :: "r"(dst), "l"(src));
}
__device__ __forceinline__ void cp_commit() {
    asm volatile("cp.async.commit_group;" ::: "memory");
}
__device__ __forceinline__ void ldsm4(uint32_t& r0, uint32_t& r1,
                                      uint32_t& r2, uint32_t& r3, uint32_t addr) {
    asm volatile("ldmatrix.sync.aligned.m8n8.x4.shared.b16 {%0,%1,%2,%3}, [%4];"
                 : "=r"(r0), "=r"(r1), "=r"(r2), "=r"(r3) : "r"(addr));
}
__device__ __forceinline__ void mma16816h(uint32_t* d, const uint32_t* a,
                                          const uint32_t* b) {
    asm volatile("mma.sync.aligned.m16n8k16.row.col.f16.f16.f16.f16 "
                 "{%0,%1}, {%2,%3,%4,%5}, {%6,%7}, {%0,%1};"
                 : "+r"(d[0]), "+r"(d[1])
                 : "r"(a[0]), "r"(a[1]), "r"(a[2]), "r"(a[3]),
                   "r"(b[0]), "r"(b[1]));
}
__device__ __forceinline__ __half2 h2ex2(__half2 x) {
    uint32_t r, xi = *(uint32_t*)&x;
    asm("ex2.approx.f16x2 %0, %1;" : "=r"(r) : "r"(xi));
    return *(__half2*)&r;
}

// ---------------- SMEM: 2-deep ring, chunk = A(128x128B) + B(256x128B) ------
#define ACH(b) ((b) * 16384)                 // A bufs @ 0, 16384
#define BCH(b) (32768 + (b) * 32768)         // B bufs @ 32768, 65536
#define CLSIH_OFF 98304                      // 128 half
#define CLSJH_OFF 98560                      // 256 half
#define SACCI_OFF 99072                      // 128 f32
#define SBCCI_OFF 99584
#define SACCJ_OFF 100096                     // 256 f32
#define SBCCJ_OFF 101120
#define SMEM_BYTES 102144                    // x2 CTAs = 204288 B/SM

// ---------------------------------------------------------------------------
// k_norm: detect + zero A/B + normalize -> f16*sqrt(EX2SC) + selfsim + cls
// ---------------------------------------------------------------------------
__global__ void k_norm(const float* __restrict__ P, const void* __restrict__ yv) {
    __shared__ int s_is64;
    const int tid  = threadIdx.x;
    const int w    = tid >> 5;
    const int lane = tid & 31;
    const int row  = blockIdx.x * 8 + w;

    if (w == 0) {
        int v = ((const int*)yv)[2 * lane + 1];
        unsigned any = __ballot_sync(0xffffffffu, v != 0);
        if (lane == 0) s_is64 = (any == 0) ? 1 : 0;
    }
    if (blockIdx.x < 32) {
        int idx = blockIdx.x * 256 + tid;
        g_A[idx] = 0.0f; g_B[idx] = 0.0f;
    }
    __syncthreads();
    const int is64 = s_is64;

    const float4* p4 = (const float4*)(P + (size_t)row * D);
    float4 v0 = p4[lane];
    float4 v1 = p4[lane + 32];

    float ss = v0.x*v0.x + v0.y*v0.y + v0.z*v0.z + v0.w*v0.w
             + v1.x*v1.x + v1.y*v1.y + v1.z*v1.z + v1.w*v1.w;
    #pragma unroll
    for (int o = 16; o; o >>= 1) ss += __shfl_xor_sync(0xffffffffu, ss, o);
    float rq = rsqrtf(ss) * SQS;

    float f[8] = {v0.x, v0.y, v0.z, v0.w, v1.x, v1.y, v1.z, v1.w};
    __half h[8];
    float sb = 0.0f;
    #pragma unroll
    for (int q = 0; q < 8; q++) {
        h[q] = __float2half_rn(f[q] * rq);
        float hf = __half2float(h[q]);
        sb += hf * hf;
    }
    #pragma unroll
    for (int o = 16; o; o >>= 1) sb += __shfl_xor_sync(0xffffffffu, sb, o);

    *(uint2*)(g_Phs + (size_t)row * D + lane * 4)       = *(uint2*)&h[0];
    *(uint2*)(g_Phs + (size_t)row * D + 128 + lane * 4) = *(uint2*)&h[4];

    if (lane == 0) {
        int c = is64 ? (int)((const long long*)yv)[row] : ((const int*)yv)[row];
        g_cls[row]     = c;
        g_clsh[row]    = __float2half_rn((float)c);
        g_selfsim[row] = sb;
    }
}

// ---------------------------------------------------------------------------
// supertile s -> (bi, bjp): for bjp, bi in [0, 2*bjp+1]
__device__ __forceinline__ void map_sup(int s, int& bi, int& bjp) {
    int b = 0, r = s;
    #pragma unroll 1
    while (r >= 2 * b + 2) { r -= 2 * b + 2; b++; }
    bjp = b; bi = r;
}

__device__ __forceinline__ void issue_chunk(uint32_t sbase, int buf, int ck,
                                            int iBase, int jBase, int tid) {
    #pragma unroll
    for (int q = 0; q < 4; q++) {
        int s  = tid + q * 256;
        int r  = s >> 3;
        int sg = s & 7;
        uint32_t soff = SW128((uint32_t)(r * 128 + sg * 16));
        cp16(sbase + ACH(buf) + soff, g_Phs + (size_t)(iBase + r) * D + ck * 64 + sg * 8);
    }
    #pragma unroll
    for (int q = 0; q < 8; q++) {
        int s  = tid + q * 256;
        int r  = s >> 3;
        int sg = s & 7;
        uint32_t soff = SW128((uint32_t)(r * 128 + sg * 16));
        cp16(sbase + BCH(buf) + soff, g_Phs + (size_t)(jBase + r) * D + ck * 64 + sg * 8);
    }
    cp_commit();
}

__device__ __forceinline__ void compute_chunk(uint32_t sbase, int buf,
                                              int m0, int n0, int lrow, int lkoff,
                                              uint32_t acc[4][8][2]) {
    const uint32_t aB = sbase + ACH(buf);
    const uint32_t bB = sbase + BCH(buf);
    #pragma unroll
    for (int ks = 0; ks < 4; ks++) {
        uint32_t afr[4][4], bfr[8][2];
        #pragma unroll
        for (int nf2 = 0; nf2 < 4; nf2++) {
            uint32_t r0, r1, r2, r3;
            uint32_t off = (uint32_t)((n0 + nf2 * 16 + lrow) * 128 + lkoff + ks * 32);
            ldsm4(r0, r1, r2, r3, bB + SW128(off));
            bfr[nf2 * 2 + 0][0] = r0; bfr[nf2 * 2 + 0][1] = r2;
            bfr[nf2 * 2 + 1][0] = r1; bfr[nf2 * 2 + 1][1] = r3;
        }
        #pragma unroll
        for (int mf = 0; mf < 4; mf++) {
            uint32_t off = (uint32_t)((m0 + mf * 16 + lrow) * 128 + lkoff + ks * 32);
            ldsm4(afr[mf][0], afr[mf][1], afr[mf][2], afr[mf][3], aB + SW128(off));
        }
        #pragma unroll
        for (int mf = 0; mf < 4; mf++)
            #pragma unroll
            for (int nf = 0; nf < 8; nf++)
                mma16816h(acc[mf][nf], afr[mf], bfr[nf]);
    }
}

// ---------------------------------------------------------------------------
// k_main: persistent, 2 CTAs/SM, 128x256 supertiles (64x64 warp tiles),
// 2-deep ring, packed-f16 epilogue, packed half2 row reduction
// ---------------------------------------------------------------------------
__global__ void __launch_bounds__(256, 2) k_main() {
    extern __shared__ __align__(128) unsigned char smem[];
    const uint32_t sbase = smem_u32(smem);
    const int tid  = threadIdx.x;
    const int wid  = tid >> 5;
    const int lane = tid & 31;
    const int STR  = gridDim.x;

    __half* clsIh = (__half*)(smem + CLSIH_OFF);
    __half* clsJh = (__half*)(smem + CLSJH_OFF);
    float*  sAccI = (float*)(smem + SACCI_OFF);
    float*  sBccI = (float*)(smem + SBCCI_OFF);
    float*  sAccJ = (float*)(smem + SACCJ_OFF);
    float*  sBccJ = (float*)(smem + SBCCJ_OFF);

    int sup = blockIdx.x;
    if (sup >= NSUP) return;

    int bi, bjp;
    map_sup(sup, bi, bjp);
    int iBase = bi * TM;
    int jBase = bjp * TNP;

    if (tid < 128) {
        clsIh[tid] = g_clsh[iBase + tid];
        sAccI[tid] = 0.0f; sBccI[tid] = 0.0f;
    }
    clsJh[tid] = g_clsh[jBase + tid];
    sAccJ[tid] = 0.0f; sBccJ[tid] = 0.0f;

    int issSup = sup, issIB = iBase, issJB = jBase, issCk = 0;
    #pragma unroll
    for (int p = 0; p < 2; p++) {
        issue_chunk(sbase, p, issCk, issIB, issJB, tid);
        if (++issCk == 4) {
            issCk = 0;
            issSup += STR;
            if (issSup < NSUP) {
                int a, b; map_sup(issSup, a, b);
                issIB = a * TM; issJB = b * TNP;
            }
        }
    }

    const int m0 = (wid >> 2) * 64;
    const int n0 = (wid & 3) * 64;
    const int lrow  = lane & 15;
    const int lkoff = (lane >> 4) * 16;
    const int gl   = lane >> 2;
    const int quad = lane & 3;

    const __half2 ONE2  = __float2half2_rn(1.0f);
    const __half2 MTWO2 = __float2half2_rn(-2.0f);

    #pragma unroll 1
    while (true) {
        const int nsup = sup + STR;
        const bool last = (nsup >= NSUP);

        const bool skipLeft = (bi == 2 * bjp + 1);
        const bool epiOn    = !(skipLeft && n0 < 128);
        const bool offdHalf = (n0 < 128) ? (bi != 2 * bjp) : (bi != 2 * bjp + 1);

        uint32_t acc[4][8][2];
        #pragma unroll
        for (int mf = 0; mf < 4; mf++)
            #pragma unroll
            for (int nf = 0; nf < 8; nf++) { acc[mf][nf][0] = 0u; acc[mf][nf][1] = 0u; }

        #pragma unroll 1
        for (int ck = 0; ck < 4; ck++) {
            asm volatile("cp.async.wait_group 1;" ::: "memory");
            __syncthreads();
            compute_chunk(sbase, ck & 1, m0, n0, lrow, lkoff, acc);
            __syncthreads();
            issue_chunk(sbase, ck & 1, issCk, issIB, issJB, tid);
            if (++issCk == 4) {
                issCk = 0;
                issSup += STR;
                if (issSup < NSUP) {
                    int a, b; map_sup(issSup, a, b);
                    issIB = a * TM; issJB = b * TNP;
                }
            }
        }

        // ---- packed-f16 epilogue ----
        __half2 cjh[8];
        #pragma unroll
        for (int nf = 0; nf < 8; nf++)
            cjh[nf] = ((const __half2*)clsJh)[(n0 >> 1) + nf * 4 + quad];

        __half2 aColH[8], bColH[8];
        #pragma unroll
        for (int nf = 0; nf < 8; nf++) {
            aColH[nf] = __float2half2_rn(0.0f);
            bColH[nf] = __float2half2_rn(0.0f);
        }

        #pragma unroll
        for (int rr = 0; rr < 2; rr++) {
            #pragma unroll
            for (int mf = 0; mf < 4; mf++) {
                const int rl = m0 + mf * 16 + gl + rr * 8;
                const __half2 cih2 = __half2half2(clsIh[rl]);
                __half2 aRowH = __float2half2_rn(0.0f);
                __half2 bRowH = __float2half2_rn(0.0f);
                #pragma unroll
                for (int nf = 0; nf < 8; nf++) {
                    __half2 s2 = *(const __half2*)&acc[mf][nf][rr];
                    __half2 m  = __heq2(cih2, cjh[nf]);
                    __half2 sc = __hfma2(m, MTWO2, ONE2);
                    __half2 v  = h2ex2(__hmul2(s2, sc));
                    __half2 vb = __hmul2(v, m);
                    __half2 va = __hsub2(v, vb);
                    aRowH = __hadd2(aRowH, va);
                    bRowH = __hadd2(bRowH, vb);
                    aColH[nf] = __hadd2(aColH[nf], va);
                    bColH[nf] = __hadd2(bColH[nf], vb);
                }
                // packed (aSum, bSum) half2 reduction across the quad
                __half2 rp = __hadd2(__lows2half2(aRowH, bRowH),
                                     __highs2half2(aRowH, bRowH));
                uint32_t r = *(uint32_t*)&rp;
                uint32_t rx = __shfl_xor_sync(0xffffffffu, r, 1);
                *(__half2*)&r = __hadd2(*(__half2*)&r, *(__half2*)&rx);
                rx = __shfl_xor_sync(0xffffffffu, r, 2);
                *(__half2*)&r = __hadd2(*(__half2*)&r, *(__half2*)&rx);
                if (epiOn && quad == 0) {
                    float2 fr = __half22float2(*(__half2*)&r);
                    atomicAdd(&sAccI[rl], fr.x);
                    atomicAdd(&sBccI[rl], fr.y);
                }
            }
        }

        if (epiOn && offdHalf) {
            #pragma unroll
            for (int nf = 0; nf < 8; nf++) {
                uint32_t a = *(uint32_t*)&aColH[nf];
                uint32_t b = *(uint32_t*)&bColH[nf];
                #pragma unroll
                for (int o = 4; o <= 16; o <<= 1) {
                    uint32_t ax = __shfl_xor_sync(0xffffffffu, a, o);
                    uint32_t bx = __shfl_xor_sync(0xffffffffu, b, o);
                    *( __half2*)&a = __hadd2(*(__half2*)&a, *(__half2*)&ax);
                    *( __half2*)&b = __hadd2(*(__half2*)&b, *(__half2*)&bx);
                }
                if (lane < 4) {
                    const int cl = n0 + nf * 8 + quad * 2;
                    float2 fa = __half22float2(*(__half2*)&a);
                    float2 fb = __half22float2(*(__half2*)&b);
                    atomicAdd(&sAccJ[cl],     fa.x);
                    atomicAdd(&sAccJ[cl + 1], fa.y);
                    atomicAdd(&sBccJ[cl],     fb.x);
                    atomicAdd(&sBccJ[cl + 1], fb.y);
                }
            }
        }

        __syncthreads();

        int nbi = bi, nbjp = bjp;
        if (!last) map_sup(nsup, nbi, nbjp);
        const int niBase = nbi * TM;
        const int njBase = nbjp * TNP;

        if (tid < 128) {
            atomicAdd(&g_A[iBase + tid], sAccI[tid]);
            atomicAdd(&g_B[iBase + tid], sBccI[tid]);
            sAccI[tid] = 0.0f; sBccI[tid] = 0.0f;
            clsIh[tid] = g_clsh[niBase + tid];
        }
        atomicAdd(&g_A[jBase + tid], sAccJ[tid]);
        atomicAdd(&g_B[jBase + tid], sBccJ[tid]);
        sAccJ[tid] = 0.0f; sBccJ[tid] = 0.0f;
        clsJh[tid] = g_clsh[njBase + tid];

        if (last) break;
        sup = nsup; bi = nbi; bjp = nbjp;
        iBase = niBase; jBase = njBase;
    }
}

// ---------------------------------------------------------------------------
// k_loss: 1024 threads — histogram, self-term subtract, empty-set, mean
// ---------------------------------------------------------------------------
__global__ void k_loss(float* __restrict__ out) {
    __shared__ float red[1024];
    __shared__ int hist[16];
    const int tid = threadIdx.x;
    if (tid < 16) hist[tid] = 0;
    __syncthreads();
    for (int r = tid; r < N; r += 1024) atomicAdd(&hist[g_cls[r] & 15], 1);
    __syncthreads();

    const float MF = __expf(0.5f * INV_T);
    float sum = 0.0f;
    for (int r = tid; r < N; r += 1024) {
        int   c   = g_cls[r] & 15;
        int   cnt = hist[c];
        float ssh = __half2float(__float2half_rn(g_selfsim[r]));
        float Bv  = g_B[r] - exp2f(-ssh);
        float Av  = (N - cnt > 0) ? g_A[r] : 1.0f;
        Bv        = (cnt - 1 > 0) ? Bv : 1.0f;
        sum += log1pf(MF * Av * Bv);
    }
    red[tid] = sum;
    __syncthreads();
    #pragma unroll
    for (int s = 512; s; s >>= 1) {
        if (tid < s) red[tid] += red[tid + s];
        __syncthreads();
    }
    if (tid == 0) out[0] = red[0] / (float)N;
}

// ---------------------------------------------------------------------------
extern "C" void kernel_launch(void* const* d_in, const int* in_sizes, int n_in,
                              void* d_out, int out_size) {
    const float* P = (const float*)d_in[0];
    const void*  y = d_in[1];
    float*     out = (float*)d_out;

    cudaFuncSetAttribute(k_main, cudaFuncAttributeMaxDynamicSharedMemorySize,
                         SMEM_BYTES);

    int sms = 148;
    cudaDeviceGetAttribute(&sms, cudaDevAttrMultiProcessorCount, 0);
    int grid = 2 * sms;
    if (grid > NSUP) grid = NSUP;

    k_norm<<<N / 8, 256>>>(P, y);
    k_main<<<grid, 256, SMEM_BYTES>>>();
    k_loss<<<1, 1024>>>(out);
}